// round 10
// baseline (speedup 1.0000x reference)
#include <cuda_runtime.h>

// LogicGatedSNN — fully fused single-pass kernel (HBM-bound, ~768 MB compulsory).
// Inputs (metadata order):
//   d_in[0] spike_input        f32 [8192]
//   d_in[1] synapse_states     f32 [8192, 8192]
//   d_in[2] membrane_potential f32 [8192]
//   d_in[3] adaptive_threshold f32 [8192]
//   d_in[4] eligibility_trace  f32 [8192, 8192]
// Output (flattened, reference return order):
//   out[0     :  8192] spikes
//   out[8192  : 16384] new_membrane
//   out[16384 : 24576] new_threshold
//   out[24576 : 24576 + O*I] new_trace (row-major)

#define IN_F   8192
#define OUT_F  8192
#define NTHR   256
#define VPT    (IN_F / NTHR / 4)   // float4 per thread = 8
#define PRE    2                   // trace float4s prefetched before reduction

__global__ __launch_bounds__(NTHR, 8)
void snn_fused_kernel(const float* __restrict__ x,
                      const float* __restrict__ syn,
                      const float* __restrict__ mp,
                      const float* __restrict__ thr,
                      const float* __restrict__ tr,
                      float* __restrict__ out)
{
    const int row = blockIdx.x;
    const int tid = threadIdx.x;

    const float4* __restrict__ x4   = reinterpret_cast<const float4*>(x);
    const float4* __restrict__ syn4 = reinterpret_cast<const float4*>(syn) + (size_t)row * (IN_F / 4);
    const float4* __restrict__ tr4  = reinterpret_cast<const float4*>(tr)  + (size_t)row * (IN_F / 4);
    float4* __restrict__ otr4 = reinterpret_cast<float4*>(out + 3 * OUT_F) + (size_t)row * (IN_F / 4);

    // ---- Phase 1: current[row] = sum_i (syn[row,i] > 50) * x[i] ----
    // syn is streaming (touched once) -> __ldcs, evict-first.
    // x is hot (reused by all 8192 CTAs) -> __ldg, keep in L1/L2.
    float sum = 0.0f;
    #pragma unroll
    for (int j = 0; j < VPT; ++j) {
        const int idx = tid + j * NTHR;           // coalesced float4 index
        const float4 s  = __ldcs(&syn4[idx]);
        const float4 xv = __ldg(&x4[idx]);
        sum += (s.x > 50.0f ? xv.x : 0.0f);
        sum += (s.y > 50.0f ? xv.y : 0.0f);
        sum += (s.z > 50.0f ? xv.z : 0.0f);
        sum += (s.w > 50.0f ? xv.w : 0.0f);
    }

    // Prefetch the first PRE trace float4s — independent of the reduction,
    // keeps the memory pipe busy across the shuffle/barrier window.
    float4 tpre[PRE];
    #pragma unroll
    for (int j = 0; j < PRE; ++j)
        tpre[j] = __ldcs(&tr4[tid + j * NTHR]);

    // warp reduce
    #pragma unroll
    for (int off = 16; off > 0; off >>= 1)
        sum += __shfl_down_sync(0xFFFFFFFFu, sum, off);

    __shared__ float warp_sums[NTHR / 32];
    __shared__ float s_spike;
    const int lane = tid & 31;
    const int wid  = tid >> 5;
    if (lane == 0) warp_sums[wid] = sum;
    __syncthreads();

    if (tid == 0) {
        float current = 0.0f;
        #pragma unroll
        for (int w = 0; w < NTHR / 32; ++w) current += warp_sums[w];

        const float v_mem = mp[row] * 0.9f + current;
        const float th    = thr[row];
        const float spike = (v_mem >= th) ? 1.0f : 0.0f;

        out[row]             = spike;                                    // spikes
        out[OUT_F + row]     = v_mem * (1.0f - spike) * 0.1f;            // new_membrane
        float nth = th + (spike - 0.1f) * 0.1f;
        nth = fminf(fmaxf(nth, 1.0f), 20.0f);
        out[2 * OUT_F + row] = nth;                                      // new_threshold

        s_spike = spike;
    }
    __syncthreads();

    // ---- Phase 2: trace update for this row (streaming read+write) ----
    const float spike = s_spike;

    #pragma unroll
    for (int j = 0; j < PRE; ++j) {
        const int idx = tid + j * NTHR;
        float4 t  = tpre[j];
        const float4 xv = __ldg(&x4[idx]);
        t.x = fminf(fmaxf(fmaf(spike, xv.x, t.x * 0.8f), 0.0f), 5.0f);
        t.y = fminf(fmaxf(fmaf(spike, xv.y, t.y * 0.8f), 0.0f), 5.0f);
        t.z = fminf(fmaxf(fmaf(spike, xv.z, t.z * 0.8f), 0.0f), 5.0f);
        t.w = fminf(fmaxf(fmaf(spike, xv.w, t.w * 0.8f), 0.0f), 5.0f);
        __stcs(&otr4[idx], t);
    }

    #pragma unroll
    for (int j = PRE; j < VPT; ++j) {
        const int idx = tid + j * NTHR;
        float4 t  = __ldcs(&tr4[idx]);
        const float4 xv = __ldg(&x4[idx]);
        t.x = fminf(fmaxf(fmaf(spike, xv.x, t.x * 0.8f), 0.0f), 5.0f);
        t.y = fminf(fmaxf(fmaf(spike, xv.y, t.y * 0.8f), 0.0f), 5.0f);
        t.z = fminf(fmaxf(fmaf(spike, xv.z, t.z * 0.8f), 0.0f), 5.0f);
        t.w = fminf(fmaxf(fmaf(spike, xv.w, t.w * 0.8f), 0.0f), 5.0f);
        __stcs(&otr4[idx], t);
    }
}

extern "C" void kernel_launch(void* const* d_in, const int* in_sizes, int n_in,
                              void* d_out, int out_size)
{
    const float* x   = (const float*)d_in[0];
    const float* syn = (const float*)d_in[1];
    const float* mp  = (const float*)d_in[2];
    const float* thr = (const float*)d_in[3];
    const float* tr  = (const float*)d_in[4];
    float* out = (float*)d_out;

    snn_fused_kernel<<<OUT_F, NTHR>>>(x, syn, mp, thr, tr, out);
}

// round 12
// speedup vs baseline: 1.0031x; 1.0031x over previous
#include <cuda_runtime.h>

// LogicGatedSNN — fully fused single-pass kernel (HBM-bound, ~768 MB compulsory).
// Measured R10: kernel 118.2us, DRAM 81.7%, 6473 GB/s — at achieved-BW roofline.
// This revision: micro-tune CTA critical path (early mp/thr loads, single-barrier
// reduction with redundant per-thread finalize).
//
// Inputs (metadata order):
//   d_in[0] spike_input        f32 [8192]
//   d_in[1] synapse_states     f32 [8192, 8192]
//   d_in[2] membrane_potential f32 [8192]
//   d_in[3] adaptive_threshold f32 [8192]
//   d_in[4] eligibility_trace  f32 [8192, 8192]
// Output (flattened, reference return order):
//   out[0     :  8192] spikes
//   out[8192  : 16384] new_membrane
//   out[16384 : 24576] new_threshold
//   out[24576 : 24576 + O*I] new_trace (row-major)

#define IN_F   8192
#define OUT_F  8192
#define NTHR   256
#define NWARPS (NTHR / 32)
#define VPT    (IN_F / NTHR / 4)   // float4 per thread = 8
#define PRE    2                   // trace float4s prefetched before reduction

__global__ __launch_bounds__(NTHR, 8)
void snn_fused_kernel(const float* __restrict__ x,
                      const float* __restrict__ syn,
                      const float* __restrict__ mp,
                      const float* __restrict__ thr,
                      const float* __restrict__ tr,
                      float* __restrict__ out)
{
    const int row = blockIdx.x;
    const int tid = threadIdx.x;

    __shared__ float warp_sums[NWARPS];
    __shared__ float s_mp, s_thr;

    // Issue the per-row scalar loads immediately, from two different warps so
    // the two LDGs proceed in parallel; they complete under phase-1 streaming.
    if (tid == 0)       s_mp  = __ldg(&mp[row]);
    else if (tid == 32) s_thr = __ldg(&thr[row]);

    const float4* __restrict__ x4   = reinterpret_cast<const float4*>(x);
    const float4* __restrict__ syn4 = reinterpret_cast<const float4*>(syn) + (size_t)row * (IN_F / 4);
    const float4* __restrict__ tr4  = reinterpret_cast<const float4*>(tr)  + (size_t)row * (IN_F / 4);
    float4* __restrict__ otr4 = reinterpret_cast<float4*>(out + 3 * OUT_F) + (size_t)row * (IN_F / 4);

    // ---- Phase 1: current[row] = sum_i (syn[row,i] > 50) * x[i] ----
    // syn is streaming (touched once) -> __ldcs, evict-first.
    // x is hot (reused by all 8192 CTAs) -> __ldg, keep in L1/L2.
    float sum = 0.0f;
    #pragma unroll
    for (int j = 0; j < VPT; ++j) {
        const int idx = tid + j * NTHR;           // coalesced float4 index
        const float4 s  = __ldcs(&syn4[idx]);
        const float4 xv = __ldg(&x4[idx]);
        sum += (s.x > 50.0f ? xv.x : 0.0f);
        sum += (s.y > 50.0f ? xv.y : 0.0f);
        sum += (s.z > 50.0f ? xv.z : 0.0f);
        sum += (s.w > 50.0f ? xv.w : 0.0f);
    }

    // Prefetch the first PRE trace float4s — independent of the reduction,
    // keeps the memory pipe busy across the shuffle/barrier window.
    float4 tpre[PRE];
    #pragma unroll
    for (int j = 0; j < PRE; ++j)
        tpre[j] = __ldcs(&tr4[tid + j * NTHR]);

    // warp reduce
    #pragma unroll
    for (int off = 16; off > 0; off >>= 1)
        sum += __shfl_down_sync(0xFFFFFFFFu, sum, off);

    const int lane = tid & 31;
    const int wid  = tid >> 5;
    if (lane == 0) warp_sums[wid] = sum;
    __syncthreads();   // single barrier: covers warp_sums, s_mp, s_thr

    // Every thread finalizes redundantly (identical order -> bit-identical),
    // removing the second barrier + broadcast from the phase transition.
    float current = 0.0f;
    #pragma unroll
    for (int w = 0; w < NWARPS; ++w) current += warp_sums[w];

    const float v_mem = s_mp * 0.9f + current;
    const float spike = (v_mem >= s_thr) ? 1.0f : 0.0f;

    if (tid == 0) {
        out[row]             = spike;                                    // spikes
        out[OUT_F + row]     = v_mem * (1.0f - spike) * 0.1f;            // new_membrane
        float nth = s_thr + (spike - 0.1f) * 0.1f;
        nth = fminf(fmaxf(nth, 1.0f), 20.0f);
        out[2 * OUT_F + row] = nth;                                      // new_threshold
    }

    // ---- Phase 2: trace update for this row (streaming read+write) ----
    #pragma unroll
    for (int j = 0; j < PRE; ++j) {
        const int idx = tid + j * NTHR;
        float4 t  = tpre[j];
        const float4 xv = __ldg(&x4[idx]);
        t.x = fminf(fmaxf(fmaf(spike, xv.x, t.x * 0.8f), 0.0f), 5.0f);
        t.y = fminf(fmaxf(fmaf(spike, xv.y, t.y * 0.8f), 0.0f), 5.0f);
        t.z = fminf(fmaxf(fmaf(spike, xv.z, t.z * 0.8f), 0.0f), 5.0f);
        t.w = fminf(fmaxf(fmaf(spike, xv.w, t.w * 0.8f), 0.0f), 5.0f);
        __stcs(&otr4[idx], t);
    }

    #pragma unroll
    for (int j = PRE; j < VPT; ++j) {
        const int idx = tid + j * NTHR;
        float4 t  = __ldcs(&tr4[idx]);
        const float4 xv = __ldg(&x4[idx]);
        t.x = fminf(fmaxf(fmaf(spike, xv.x, t.x * 0.8f), 0.0f), 5.0f);
        t.y = fminf(fmaxf(fmaf(spike, xv.y, t.y * 0.8f), 0.0f), 5.0f);
        t.z = fminf(fmaxf(fmaf(spike, xv.z, t.z * 0.8f), 0.0f), 5.0f);
        t.w = fminf(fmaxf(fmaf(spike, xv.w, t.w * 0.8f), 0.0f), 5.0f);
        __stcs(&otr4[idx], t);
    }
}

extern "C" void kernel_launch(void* const* d_in, const int* in_sizes, int n_in,
                              void* d_out, int out_size)
{
    const float* x   = (const float*)d_in[0];
    const float* syn = (const float*)d_in[1];
    const float* mp  = (const float*)d_in[2];
    const float* thr = (const float*)d_in[3];
    const float* tr  = (const float*)d_in[4];
    float* out = (float*)d_out;

    snn_fused_kernel<<<OUT_F, NTHR>>>(x, syn, mp, thr, tr, out);
}